// round 1
// baseline (speedup 1.0000x reference)
#include <cuda_runtime.h>
#include <math.h>

#define Bb      256
#define Nn      8192
#define SD      14
#define ROWS    256
#define THREADS 256
#define CHUNKS  (Nn / ROWS)   // 32

// accumulators: 0=sum werr[0:6], 1=sum werr[6:13], 2=sum werr[13],
//               3=sum residual^2, 4=sum quat, 5=sum massflow, 6=sum bc
__device__ double g_acc[7];
__device__ int    g_tidx;

// ---------------------------------------------------------------------------
// Kernel 1: zero accumulators + argmin |t[0,:,0]|
// ---------------------------------------------------------------------------
__global__ void k_init(const float* __restrict__ t)
{
    if (threadIdx.x < 7) g_acc[threadIdx.x] = 0.0;

    __shared__ float svals[THREADS];
    __shared__ int   sidx[THREADS];

    float best = 3.402823466e+38f;
    int   bi   = 0;
    for (int i = threadIdx.x; i < Nn; i += THREADS) {
        float v = fabsf(t[i]);
        if (v < best) { best = v; bi = i; }   // first occurrence wins (i increasing)
    }
    svals[threadIdx.x] = best;
    sidx[threadIdx.x]  = bi;
    __syncthreads();
    for (int s = THREADS / 2; s > 0; s >>= 1) {
        if (threadIdx.x < s) {
            float v2 = svals[threadIdx.x + s];
            int   i2 = sidx[threadIdx.x + s];
            if (v2 < svals[threadIdx.x] ||
                (v2 == svals[threadIdx.x] && i2 < sidx[threadIdx.x])) {
                svals[threadIdx.x] = v2;
                sidx[threadIdx.x]  = i2;
            }
        }
        __syncthreads();
    }
    if (threadIdx.x == 0) g_tidx = sidx[0];
}

// ---------------------------------------------------------------------------
// Kernel 2: fused loss reduction. One block = 256 rows of one batch element.
// ---------------------------------------------------------------------------
__global__ __launch_bounds__(THREADS)
void k_main(const float* __restrict__ pred,
            const float* __restrict__ truev,
            const float* __restrict__ t,
            const float* __restrict__ ctrl)
{
    // padded rows: 15 floats (stride 15 coprime with 32 banks -> conflict-free)
    __shared__ float sp[(ROWS + 2) * 15];   // pred chunk + 2 halo rows
    __shared__ float st[ROWS * 15];         // true chunk
    __shared__ float sc[ROWS * 5];          // control chunk (padded 4 -> 5)
    __shared__ double red[THREADS / 32][7];

    const int b     = blockIdx.x >> 5;          // /CHUNKS
    const int chunk = blockIdx.x & (CHUNKS - 1);
    const int n0    = chunk * ROWS;
    const int tid   = threadIdx.x;

    const float* pbase = pred  + ((size_t)b * Nn + n0) * SD;
    const float* tbase = truev + ((size_t)b * Nn + n0) * SD;
    const float* cbase = ctrl  + ((size_t)b * Nn + n0) * 4;

    // coalesced staging (scalar loads, consecutive threads -> consecutive addrs)
    #pragma unroll
    for (int i = tid; i < ROWS * SD; i += THREADS) {
        int r = i / SD, c = i - r * SD;
        sp[(r + 1) * 15 + c] = pbase[i];
        st[r * 15 + c]       = tbase[i];
    }
    #pragma unroll
    for (int i = tid; i < ROWS * 4; i += THREADS) {
        int r = i >> 2, c = i & 3;
        sc[r * 5 + c] = cbase[i];
    }
    // halo rows
    if (n0 > 0 && tid < SD)                      sp[tid]                 = pbase[tid - SD];
    if (n0 + ROWS < Nn && tid >= 32 && tid < 32 + SD)
                                                 sp[(ROWS + 1) * 15 + (tid - 32)] = pbase[ROWS * SD + (tid - 32)];
    __syncthreads();

    const int n = n0 + tid;                       // global time index (one row/thread)
    const float* s  = &sp[(tid + 1) * 15];
    const float* tr = &st[tid * 15];
    const float* u  = &sc[tid * 5];

    // ---- data loss partials ----
    float sA = 0.f, sB = 0.f;
    #pragma unroll
    for (int i = 0; i < 6; i++) { float d = s[i] - tr[i]; sA += d * d; }
    #pragma unroll
    for (int i = 6; i < 13; i++) { float d = s[i] - tr[i]; sB += d * d; }
    float d13 = s[13] - tr[13];
    float sC  = d13 * d13;

    // ---- quaternion norm loss ----
    const float q0 = s[6], q1 = s[7], q2 = s[8], q3 = s[9];
    float qn = sqrtf(q0 * q0 + q1 * q1 + q2 * q2 + q3 * q3);
    float dq = qn - 1.0f;
    float sQ = dq * dq;

    // ---- mass flow loss ----
    float sMF = 0.f;
    if (n < Nn - 1) {
        float mnext = sp[(tid + 2) * 15 + 13];
        float dmf   = mnext - s[13];
        sMF = dmf > 0.f ? dmf : 0.f;
    }

    // ---- finite difference ----
    const float* lo;
    const float* hi;
    float dt;
    if (n == 0)            { lo = s;                      hi = &sp[(tid + 2) * 15]; dt = t[1]      - t[0]; }
    else if (n == Nn - 1)  { lo = &sp[tid * 15];          hi = s;                    dt = t[Nn - 1] - t[Nn - 2]; }
    else                   { lo = &sp[tid * 15];          hi = &sp[(tid + 2) * 15];  dt = t[n + 1]  - t[n - 1]; }
    const float inv_dt = 1.0f / (dt + 1e-12f);

    // ---- dynamics ----
    const float vx = s[3], vy = s[4], vz = s[5];
    const float wx = s[10], wy = s[11], wz = s[12];
    const float m  = s[13];

    const float thrust = u[0] * 1000000.0f;
    const float bzx = 2.0f * (q1 * q3 + q0 * q2);
    const float bzy = 2.0f * (q2 * q3 - q0 * q1);
    const float bzz = 1.0f - 2.0f * (q1 * q1 + q2 * q2);
    const float speed = sqrtf(vx * vx + vy * vy + vz * vz + 1e-12f);
    const float dragc = -0.30625f * speed;     // -0.5*rho*Cd*A*speed
    const float invm  = 1.0f / m;

    float dyn[SD];
    dyn[0] = vx; dyn[1] = vy; dyn[2] = vz;
    dyn[3] = (thrust * bzx + dragc * vx) * invm;
    dyn[4] = (thrust * bzy + dragc * vy) * invm;
    dyn[5] = (thrust * bzz + dragc * vz) * invm - 9.80665f;
    dyn[6] = 0.5f * (-q1 * wx - q2 * wy - q3 * wz);
    dyn[7] = 0.5f * ( q0 * wx + q2 * wz - q3 * wy);
    dyn[8] = 0.5f * ( q0 * wy - q1 * wz + q3 * wx);
    dyn[9] = 0.5f * ( q0 * wz + q1 * wy - q2 * wx);
    dyn[10] = (u[1] * 10000.0f + 4000.0f * wy * wz) * (1.0f / 5000.0f);
    dyn[11] = (u[2] * 10000.0f - 4000.0f * wz * wx) * (1.0f / 5000.0f);
    dyn[12] = (u[3] * 10000.0f) * (1.0f / 1000.0f);
    dyn[13] = -thrust * (1.0f / (300.0f * 9.80665f));

    float sP = 0.f;
    #pragma unroll
    for (int i = 0; i < SD; i++) {
        float r = (hi[i] - lo[i]) * inv_dt - dyn[i];
        sP += r * r;
    }

    // ---- boundary-condition loss (row == time_idx) ----
    float sBC = (n == g_tidx) ? (sA + sB + sC) : 0.f;

    // ---- block reduction in fp64 ----
    double v[7] = { (double)sA, (double)sB, (double)sC, (double)sP,
                    (double)sQ, (double)sMF, (double)sBC };
    const int lane = tid & 31, warp = tid >> 5;
    #pragma unroll
    for (int off = 16; off > 0; off >>= 1)
        #pragma unroll
        for (int j = 0; j < 7; j++)
            v[j] += __shfl_down_sync(0xffffffffu, v[j], off);
    if (lane == 0)
        #pragma unroll
        for (int j = 0; j < 7; j++) red[warp][j] = v[j];
    __syncthreads();
    if (warp == 0) {
        #pragma unroll
        for (int j = 0; j < 7; j++)
            v[j] = (lane < THREADS / 32) ? red[lane][j] : 0.0;
        #pragma unroll
        for (int off = 4; off > 0; off >>= 1)
            #pragma unroll
            for (int j = 0; j < 7; j++)
                v[j] += __shfl_down_sync(0xffffffffu, v[j], off);
        if (lane == 0)
            #pragma unroll
            for (int j = 0; j < 7; j++)
                atomicAdd(&g_acc[j], v[j]);
    }
}

// ---------------------------------------------------------------------------
// Kernel 3: finalize -> 6 floats
// ---------------------------------------------------------------------------
__global__ void k_final(float* __restrict__ out)
{
    if (threadIdx.x == 0) {
        const double BN = (double)Bb * (double)Nn;
        double L_data = g_acc[0] / (BN * 6.0) + g_acc[1] / (BN * 7.0) + g_acc[2] / BN;
        double L_phys = g_acc[3] / (BN * 14.0);
        double L_quat = g_acc[4] / BN;
        double L_mf   = g_acc[5] / ((double)Bb * (double)(Nn - 1));
        double L_bc   = g_acc[6] / ((double)Bb * 14.0);
        double total  = L_data + 0.1 * L_phys + L_bc + 0.01 * L_quat + 0.01 * L_mf;
        out[0] = (float)total;
        out[1] = (float)L_data;
        out[2] = (float)L_phys;
        out[3] = (float)L_bc;
        out[4] = (float)L_quat;
        out[5] = (float)L_mf;
    }
}

// ---------------------------------------------------------------------------
extern "C" void kernel_launch(void* const* d_in, const int* in_sizes, int n_in,
                              void* d_out, int out_size)
{
    const float* pred = (const float*)d_in[0];
    const float* tru  = (const float*)d_in[1];
    const float* t    = (const float*)d_in[2];
    const float* ctrl = (const float*)d_in[3];
    float* out = (float*)d_out;

    k_init<<<1, THREADS>>>(t);
    k_main<<<Bb * CHUNKS, THREADS>>>(pred, tru, t, ctrl);
    k_final<<<1, 32>>>(out);
}